// round 14
// baseline (speedup 1.0000x reference)
#include <cuda_runtime.h>
#include <math.h>

#define NE     200000
#define NI     100000
#define DIM    64
#define NEDGE  1500000
#define KEDGE  256
#define KITEM  100
#define SCALE  0.08838834764831845f   // 1/(2*sqrt(32))

#define CAND_MAX 2048
#define NBINS    8192                 // 13-bit key prefix
#define BIN_SHIFT 19

// topk persistent kernel: 592 blocks = 148 SM x 4 (co-resident)
#define TE_BLOCKS 512
#define TI_BLOCKS 80
#define NB_TOTAL  (TE_BLOCKS + TI_BLOCKS)
#define TE_STRIDE (TE_BLOCKS * 256)           // 131072 threads (edge part)
#define TE_PAIRS  6                           // 6 pairs = 12 edges/thread
#define TI_STRIDE (TI_BLOCKS * 256)           // 20480 threads (item part)
#define TI_PAIRS  3                           // 3 pairs = 6 items/thread

// edge kernel: grid-stride, 8 edges per warp per step (standalone: high occ)
#define EDGE_BLOCKS 1184                      // 148 * 8
#define EDGE_WARPS  (EDGE_BLOCKS * 8)         // 9472
#define EDGE_GROUPS (NEDGE / 8)               // 187500

// smem bank swizzle for the select stage (conflict-free both directions)
#define SWZ(x) ((x) ^ (((x) >> 5) & 31))

// ---------------- scratch ----------------
__device__ float    g_proj[NE * DIM];
__device__ float    g_ex[NEDGE];
__device__ float    g_gum[NEDGE];             // precomputed log(-log(u))
__device__ float    g_dd[2 * NE];             // [denom, deg]
__device__ float    g_sumnode[NE];

__device__ unsigned g_bins_e[NBINS];
__device__ unsigned g_bins_i[NBINS];
__device__ int      g_cnt[2];
__device__ unsigned long long g_cand_e[CAND_MAX];
__device__ unsigned long long g_cand_i[CAND_MAX];

__device__ unsigned g_bar_cnt;                // zero-init, self-resetting
__device__ volatile unsigned g_bar_gen;

// ---------------- helpers ----------------
__device__ __forceinline__ unsigned fkey(float f) {
    unsigned u = __float_as_uint(f);
    return (u & 0x80000000u) ? ~u : (u | 0x80000000u);
}
__device__ __forceinline__ float keyf(unsigned k) {
    unsigned u = (k & 0x80000000u) ? (k & 0x7FFFFFFFu) : ~k;
    return __uint_as_float(u);
}

#define PACK2(out, lo, hi) \
    asm("mov.b64 %0, {%1, %2};" : "=l"(out) : "f"(lo), "f"(hi))
#define UNPACK2(lo, hi, in) \
    asm("mov.b64 {%0, %1}, %2;" : "=f"(lo), "=f"(hi) : "l"(in))
#define FMA2(d, a, b, c) \
    asm("fma.rn.f32x2 %0, %1, %2, %3;" : "=l"(d) : "l"(a), "l"(b), "l"(c))

__device__ __forceinline__ void grid_sync() {
    __threadfence();
    __syncthreads();
    if (threadIdx.x == 0) {
        unsigned gen = g_bar_gen;
        if (atomicAdd(&g_bar_cnt, 1u) == gridDim.x - 1) {
            g_bar_cnt = 0u;
            __threadfence();
            g_bar_gen = gen + 1u;
        } else {
            while (g_bar_gen == gen) { __nanosleep(64); }
        }
        __threadfence();
    }
    __syncthreads();
}

// accurate-cheap -log(u): series near 1 (MUFU abs error would wreck the top
// gumbel candidates where x = -log u ~ 1e-6), __logf elsewhere
__device__ __forceinline__ float neglog(float u) {
    float t = u - 1.0f;
    float p = fmaf(t, -0.16666667f, 0.2f);
    p = fmaf(t, p, -0.25f);
    p = fmaf(t, p, 0.33333333f);
    p = fmaf(t, p, -0.5f);
    p = fmaf(t, p, 1.0f);
    float ser = -t * p;
    float fast = -__logf(u);
    return (u > 0.84f) ? ser : fast;
}

// every block runs this (deterministic -> same answer everywhere).
// bins staged coalesced into swizzled smem, then 2-level suffix select.
__device__ unsigned select13s(const unsigned* bins, int K, unsigned* s_bins) {
    __shared__ unsigned s_sum[256];
    __shared__ int s_chunk, s_krem;
    __shared__ unsigned s_kth;
    int t = threadIdx.x;
    #pragma unroll
    for (int i = 0; i < 32; i++) {
        int L = i * 256 + t;                  // coalesced L2 read
        s_bins[SWZ(L)] = __ldcg(&bins[L]);
    }
    __syncthreads();
    unsigned sum = 0;
    #pragma unroll
    for (int i = 0; i < 32; i++) sum += s_bins[SWZ(t * 32 + i)];   // conflict-free
    s_sum[t] = sum;
    __syncthreads();
    #pragma unroll
    for (int off = 1; off < 256; off <<= 1) {
        unsigned v = s_sum[t];
        if (t + off < 256) v += s_sum[t + off];
        __syncthreads();
        s_sum[t] = v;
        __syncthreads();
    }
    unsigned incl = s_sum[t];                 // chunks t..255
    unsigned above = incl - sum;
    if ((int)above < K && K <= (int)incl) { s_chunk = t; s_krem = K - (int)above; }
    __syncthreads();
    int chunk = s_chunk, kRem = s_krem;
    if (t < 32) {                             // warp 0: refine within chunk
        unsigned c = s_bins[SWZ((chunk << 5) + t)];
        unsigned run = c;
        #pragma unroll
        for (int off = 1; off < 32; off <<= 1) {
            unsigned v = __shfl_down_sync(0xffffffffu, run, off);
            if (t + off < 32) run += v;
        }
        unsigned ab = run - c;                // bins above this one in chunk
        if ((int)ab < kRem && kRem <= (int)run)
            s_kth = (unsigned)((chunk << 5) + t) << BIN_SHIFT;
    }
    __syncthreads();
    return s_kth;
}

// one block: bitonic-sort candidates (value desc, idx asc), emit top K
__device__ void sort_emit(unsigned long long* s, unsigned long long* cand,
                          volatile int* cntp,
                          float* __restrict__ outV, float* __restrict__ outI, int K) {
    int cnt = *cntp;
    if (cnt > CAND_MAX) cnt = CAND_MAX;
    int n2 = 1; while (n2 < cnt) n2 <<= 1;
    for (int i = threadIdx.x; i < n2; i += 256)
        s[i] = (i < cnt) ? ((volatile unsigned long long*)cand)[i]
                         : 0xFFFFFFFFFFFFFFFFull;
    __syncthreads();
    for (int k = 2; k <= n2; k <<= 1) {
        for (int j = k >> 1; j > 0; j >>= 1) {
            for (int i = threadIdx.x; i < n2; i += 256) {
                int p = i ^ j;
                if (p > i) {
                    bool up = ((i & k) == 0);
                    unsigned long long a = s[i], b = s[p];
                    if ((a > b) == up) { s[i] = b; s[p] = a; }
                }
            }
            __syncthreads();
        }
    }
    for (int t = threadIdx.x; t < K; t += 256) {
        unsigned long long cc = s[t];
        outV[t] = keyf(~(unsigned)(cc >> 32));
        outI[t] = (float)(unsigned)(cc & 0xFFFFFFFFu);
    }
}

// ---------------- 1) projection: 128 thr, 8x4 tile + fused init/gumbel ------
// (R10-proven config: regs 85, occ 28.5%, 40us — frozen)
__global__ void __launch_bounds__(128)
k_proj(const float* __restrict__ emb, const float* __restrict__ W,
       const float* __restrict__ noise) {
    __shared__ float sE[64 * 68];
    __shared__ float sW[64 * 64];
    int tid = threadIdx.x;               // 128
    int base = blockIdx.x * 64 * DIM;
    int eb = blockIdx.x * 64;

    g_dd[2 * eb + tid] = 0.0f;
    if (tid < 64) g_sumnode[eb + tid] = 0.0f;
    if (blockIdx.x < 64)        g_bins_e[blockIdx.x * 128 + tid] = 0u;
    else if (blockIdx.x < 128)  g_bins_i[(blockIdx.x - 64) * 128 + tid] = 0u;
    else if (blockIdx.x == 128 && tid < 2) g_cnt[tid] = 0;

    const float4* ev = (const float4*)(emb + base);
    const float4* wv = (const float4*)W;
    #pragma unroll
    for (int i = tid; i < 1024; i += 128) {
        int r = i >> 4, c = i & 15;
        *(float4*)&sE[r * 68 + c * 4] = ev[i];
        ((float4*)sW)[i] = wv[i];
    }
    __syncthreads();

    // gumbel precompute: 1.5M edges over 400k threads, 4 coalesced strides
    {
        int t0 = blockIdx.x * 128 + tid;
        #pragma unroll
        for (int k = 0; k < 4; k++) {
            int e = t0 + k * 400000;
            if (e < NEDGE) g_gum[e] = __logf(neglog(__ldcs(&noise[e])));
        }
    }

    int tr = tid >> 4;
    int tc = tid & 15;

    unsigned long long a01[8], a23[8];
    #pragma unroll
    for (int i = 0; i < 8; i++) { a01[i] = 0ull; a23[i] = 0ull; }

    #pragma unroll
    for (int d4 = 0; d4 < 16; d4++) {
        unsigned long long w01[4], w23[4];
        #pragma unroll
        for (int j = 0; j < 4; j++) {
            float4 w = *(const float4*)&sW[(d4 * 4 + j) * 64 + tc * 4];
            PACK2(w01[j], w.x, w.y);
            PACK2(w23[j], w.z, w.w);
        }
        #pragma unroll
        for (int i = 0; i < 8; i++) {
            float4 e = *(const float4*)&sE[(tr * 8 + i) * 68 + d4 * 4];
            unsigned long long ee;
            PACK2(ee, e.x, e.x); FMA2(a01[i], ee, w01[0], a01[i]); FMA2(a23[i], ee, w23[0], a23[i]);
            PACK2(ee, e.y, e.y); FMA2(a01[i], ee, w01[1], a01[i]); FMA2(a23[i], ee, w23[1], a23[i]);
            PACK2(ee, e.z, e.z); FMA2(a01[i], ee, w01[2], a01[i]); FMA2(a23[i], ee, w23[2], a23[i]);
            PACK2(ee, e.w, e.w); FMA2(a01[i], ee, w01[3], a01[i]); FMA2(a23[i], ee, w23[3], a23[i]);
        }
    }
    #pragma unroll
    for (int i = 0; i < 8; i++) {
        float4 o;
        UNPACK2(o.x, o.y, a01[i]);
        UNPACK2(o.z, o.w, a23[i]);
        *(float4*)&g_proj[base + (tr * 8 + i) * 64 + tc * 4] = o;
    }
}

// ---------------- 2) edge kernel: 4 lanes/edge, 8 edges/warp, grid-stride ---
__device__ __forceinline__ void edge8(int grp,
                                      const int* __restrict__ head,
                                      const int* __restrict__ tail,
                                      const int* __restrict__ etype,
                                      const float* __restrict__ rel,
                                      int g, int sub) {
    int e = grp * 8 + g;
    int h = __ldcs(&head[e]);
    int t = __ldcs(&tail[e]);
    int r = __ldcs(&etype[e]) - 1;

    const float4* Q = (const float4*)&g_proj[(size_t)h << 6];
    const float4* K = (const float4*)&g_proj[(size_t)t << 6];
    const float4* R = (const float4*)rel + ((size_t)r << 4);

    float s = 0.0f;
    #pragma unroll
    for (int j = 0; j < 4; j++) {
        float4 q = __ldg(Q + sub + 4 * j);
        float4 k = __ldg(K + sub + 4 * j);
        float4 v = __ldg(R + sub + 4 * j);
        s += q.x * k.x * v.x + q.y * k.y * v.y + q.z * k.z * v.z + q.w * k.w * v.w;
    }
    s += __shfl_xor_sync(0xffffffffu, s, 1);
    s += __shfl_xor_sync(0xffffffffu, s, 2);

    float lg = s * SCALE;
    if (sub == 0) {
        float ex = __expf(lg);
        g_ex[e] = ex;
        atomicAdd(&g_dd[2 * h], ex);
    } else if (sub == 1) {
        atomicAdd(&g_dd[2 * h + 1], 1.0f);
    } else if (sub == 2) {
        atomicAdd(&g_sumnode[h], lg);
    } else {
        atomicAdd(&g_sumnode[t], lg);
    }
}

__global__ void __launch_bounds__(256)
k_edge(const int* __restrict__ head, const int* __restrict__ tail,
       const int* __restrict__ etype, const float* __restrict__ rel) {
    int warp = blockIdx.x * 8 + (threadIdx.x >> 5);
    int lane = threadIdx.x & 31;
    int g = lane >> 2;
    int sub = lane & 3;

    #pragma unroll 4
    for (int grp = warp; grp < EDGE_GROUPS; grp += EDGE_WARPS)
        edge8(grp, head, tail, etype, rel, g, sub);
}

// warp-aggregated smem histogram add
__device__ __forceinline__ void hist_add(unsigned* sh, unsigned bin) {
    unsigned m = __match_any_sync(0xffffffffu, bin);
    int leader = __ffs(m) - 1;
    if ((int)(threadIdx.x & 31) == leader) atomicAdd(&sh[bin], __popc(m));
}

// ---------------- 3) fused topk (edges + items), 2 grid syncs ---------------
__global__ void __launch_bounds__(256, 4)
k_topk(const int* __restrict__ head,
       float* __restrict__ out,
       float* __restrict__ tkv, float* __restrict__ tki,
       float* __restrict__ itv, float* __restrict__ iti) {
    __shared__ unsigned long long s_buf[NBINS / 2];   // 32KB: hist / select / sort
    unsigned* s_hist = (unsigned*)s_buf;
    unsigned key[2 * TE_PAIRS];
    int tid = threadIdx.x;
    bool isE = blockIdx.x < TE_BLOCKS;

    #pragma unroll
    for (int i = 0; i < NBINS / 256; i++) s_hist[tid + i * 256] = 0u;
    __syncthreads();

    // ---- phase A: pair-vectorized keys + warp-aggregated smem hist ----
    if (isE) {
        int gtid = blockIdx.x * 256 + tid;
        #pragma unroll
        for (int p = 0; p < TE_PAIRS; p++) {
            int pr = gtid + p * TE_STRIDE;            // pair index
            unsigned k0 = 0u, k1 = 0u;
            if (pr < NEDGE / 2) {
                int2  hh   = __ldcs((const int2*)head + pr);
                float2 ex2 = __ldcs((const float2*)g_ex + pr);
                float2 gm2 = __ldcs((const float2*)g_gum + pr);
                float2 d0  = *(const float2*)&g_dd[2 * hh.x];
                float2 d1  = *(const float2*)&g_dd[2 * hh.y];
                float sc0 = ex2.x * __fdividef(d0.y, d0.x);
                float sc1 = ex2.y * __fdividef(d1.y, d1.x);
                *(float2*)&out[2 * pr] = make_float2(sc0, sc1);
                k0 = fkey(sc0 - gm2.x);
                k1 = fkey(sc1 - gm2.y);
            }
            key[2 * p] = k0; key[2 * p + 1] = k1;
            hist_add(s_hist, k0 >> BIN_SHIFT);
            hist_add(s_hist, k1 >> BIN_SHIFT);
        }
        __syncthreads();
        #pragma unroll
        for (int i = 0; i < NBINS / 256; i++) {
            unsigned c = s_hist[tid + i * 256];
            if (c) atomicAdd(&g_bins_e[tid + i * 256], c);
        }
    } else {
        int gtid = (blockIdx.x - TE_BLOCKS) * 256 + tid;
        #pragma unroll
        for (int p = 0; p < TI_PAIRS; p++) {
            int pr = gtid + p * TI_STRIDE;
            unsigned k0 = 0u, k1 = 0u;
            if (pr < NI / 2) {
                float2 v = __ldcs((const float2*)g_sumnode + pr);
                k0 = fkey(v.x);
                k1 = fkey(v.y);
            }
            key[2 * p] = k0; key[2 * p + 1] = k1;
            hist_add(s_hist, k0 >> BIN_SHIFT);
            hist_add(s_hist, k1 >> BIN_SHIFT);
        }
        __syncthreads();
        #pragma unroll
        for (int i = 0; i < NBINS / 256; i++) {
            unsigned c = s_hist[tid + i * 256];
            if (c) atomicAdd(&g_bins_i[tid + i * 256], c);
        }
    }
    grid_sync();

    // ---- phase B: every block computes its threshold locally ----
    unsigned kth = isE ? select13s(g_bins_e, KEDGE, (unsigned*)s_buf)
                       : select13s(g_bins_i, KITEM, (unsigned*)s_buf);

    // ---- phase C: collect candidates >= threshold ----
    if (isE) {
        int gtid = blockIdx.x * 256 + tid;
        #pragma unroll
        for (int i = 0; i < 2 * TE_PAIRS; i++) {
            unsigned k = key[i];
            if (k >= kth) {
                int e = 2 * (gtid + (i >> 1) * TE_STRIDE) + (i & 1);
                int p = atomicAdd(&g_cnt[0], 1);
                if (p < CAND_MAX)
                    g_cand_e[p] = (((unsigned long long)(~k)) << 32) | (unsigned)e;
            }
        }
    } else {
        int gtid = (blockIdx.x - TE_BLOCKS) * 256 + tid;
        #pragma unroll
        for (int i = 0; i < 2 * TI_PAIRS; i++) {
            unsigned k = key[i];
            if (k >= kth) {
                int e = 2 * (gtid + (i >> 1) * TI_STRIDE) + (i & 1);
                int p = atomicAdd(&g_cnt[1], 1);
                if (p < CAND_MAX)
                    g_cand_i[p] = (((unsigned long long)(~k)) << 32) | (unsigned)e;
            }
        }
    }
    grid_sync();

    // ---- phase D: sort + emit ----
    if (blockIdx.x == 0)
        sort_emit(s_buf, g_cand_e, &g_cnt[0], tkv, tki, KEDGE);
    else if (blockIdx.x == TE_BLOCKS)
        sort_emit(s_buf, g_cand_i, &g_cnt[1], itv, iti, KITEM);
}

// ---------------- host ----------------
extern "C" void kernel_launch(void* const* d_in, const int* in_sizes, int n_in,
                              void* d_out, int out_size) {
    const float* emb   = (const float*)d_in[0];
    const float* WQ    = (const float*)d_in[1];
    const float* rel   = (const float*)d_in[2];
    const float* noise = (const float*)d_in[3];
    const int*   eidx  = (const int*)d_in[4];
    const int*   etype = (const int*)d_in[5];
    const int* head = eidx;
    const int* tail = eidx + NEDGE;
    float* out = (float*)d_out;

    float* out_tkv = out + NEDGE;
    float* out_tki = out + NEDGE + KEDGE;
    float* out_itv = out + NEDGE + 2 * KEDGE;
    float* out_iti = out + NEDGE + 2 * KEDGE + KITEM;

    k_proj<<<NE / 64, 128>>>(emb, WQ, noise);
    k_edge<<<EDGE_BLOCKS, 256>>>(head, tail, etype, rel);
    k_topk<<<NB_TOTAL, 256>>>(head, out, out_tkv, out_tki, out_itv, out_iti);
}

// round 15
// speedup vs baseline: 1.0103x; 1.0103x over previous
#include <cuda_runtime.h>
#include <math.h>

#define NE     200000
#define NI     100000
#define DIM    64
#define NEDGE  1500000
#define KEDGE  256
#define KITEM  100
#define SCALE  0.08838834764831845f   // 1/(2*sqrt(32))

#define CAND_MAX 2048
#define NBINS    8192                 // 13-bit key prefix
#define BIN_SHIFT 19

// topk persistent kernel: 592 blocks = 148 SM x 4 (co-resident)
// rebalanced split: edge blocks finish phase A ~5x slower than item blocks
#define TE_BLOCKS 544
#define TI_BLOCKS 48
#define NB_TOTAL  (TE_BLOCKS + TI_BLOCKS)     // 592
#define TE_STRIDE (TE_BLOCKS * 256)           // 139264 threads (edge part)
#define TE_PAIRS  6                           // 6*139264 = 835584 >= 750000 pairs
#define TI_STRIDE (TI_BLOCKS * 256)           // 12288 threads (item part)
#define TI_PAIRS  5                           // 5*12288 = 61440 >= 50000 pairs

// edge kernel: grid-stride, 8 edges per warp per step (standalone: high occ)
#define EDGE_BLOCKS 1184                      // 148 * 8
#define EDGE_WARPS  (EDGE_BLOCKS * 8)         // 9472
#define EDGE_GROUPS (NEDGE / 8)               // 187500

// smem bank swizzle for the select stage (conflict-free both directions)
#define SWZ(x) ((x) ^ (((x) >> 5) & 31))

// ---------------- scratch ----------------
__device__ float    g_proj[NE * DIM];
__device__ float    g_ex[NEDGE];
__device__ float    g_gum[NEDGE];             // precomputed log(-log(u))
__device__ float    g_dd[2 * NE];             // [denom, deg]
__device__ float    g_sumnode[NE];

__device__ unsigned g_bins_e[NBINS];
__device__ unsigned g_bins_i[NBINS];
__device__ int      g_cnt[2];
__device__ unsigned long long g_cand_e[CAND_MAX];
__device__ unsigned long long g_cand_i[CAND_MAX];

__device__ unsigned g_bar_cnt;                // zero-init, self-resetting
__device__ volatile unsigned g_bar_gen;

// ---------------- helpers ----------------
__device__ __forceinline__ unsigned fkey(float f) {
    unsigned u = __float_as_uint(f);
    return (u & 0x80000000u) ? ~u : (u | 0x80000000u);
}
__device__ __forceinline__ float keyf(unsigned k) {
    unsigned u = (k & 0x80000000u) ? (k & 0x7FFFFFFFu) : ~k;
    return __uint_as_float(u);
}

#define PACK2(out, lo, hi) \
    asm("mov.b64 %0, {%1, %2};" : "=l"(out) : "f"(lo), "f"(hi))
#define UNPACK2(lo, hi, in) \
    asm("mov.b64 {%0, %1}, %2;" : "=f"(lo), "=f"(hi) : "l"(in))
#define FMA2(d, a, b, c) \
    asm("fma.rn.f32x2 %0, %1, %2, %3;" : "=l"(d) : "l"(a), "l"(b), "l"(c))

__device__ __forceinline__ void grid_sync() {
    __threadfence();
    __syncthreads();
    if (threadIdx.x == 0) {
        unsigned gen = g_bar_gen;
        if (atomicAdd(&g_bar_cnt, 1u) == gridDim.x - 1) {
            g_bar_cnt = 0u;
            __threadfence();
            g_bar_gen = gen + 1u;
        } else {
            while (g_bar_gen == gen) { __nanosleep(64); }
        }
        __threadfence();
    }
    __syncthreads();
}

// accurate-cheap -log(u): series near 1 (MUFU abs error would wreck the top
// gumbel candidates where x = -log u ~ 1e-6), __logf elsewhere
__device__ __forceinline__ float neglog(float u) {
    float t = u - 1.0f;
    float p = fmaf(t, -0.16666667f, 0.2f);
    p = fmaf(t, p, -0.25f);
    p = fmaf(t, p, 0.33333333f);
    p = fmaf(t, p, -0.5f);
    p = fmaf(t, p, 1.0f);
    float ser = -t * p;
    float fast = -__logf(u);
    return (u > 0.84f) ? ser : fast;
}

// every block runs this (deterministic -> same answer everywhere).
// bins staged coalesced into swizzled smem, then 2-level suffix select.
__device__ unsigned select13s(const unsigned* bins, int K, unsigned* s_bins) {
    __shared__ unsigned s_sum[256];
    __shared__ int s_chunk, s_krem;
    __shared__ unsigned s_kth;
    int t = threadIdx.x;
    #pragma unroll
    for (int i = 0; i < 32; i++) {
        int L = i * 256 + t;                  // coalesced L2 read
        s_bins[SWZ(L)] = __ldcg(&bins[L]);
    }
    __syncthreads();
    unsigned sum = 0;
    #pragma unroll
    for (int i = 0; i < 32; i++) sum += s_bins[SWZ(t * 32 + i)];   // conflict-free
    s_sum[t] = sum;
    __syncthreads();
    #pragma unroll
    for (int off = 1; off < 256; off <<= 1) {
        unsigned v = s_sum[t];
        if (t + off < 256) v += s_sum[t + off];
        __syncthreads();
        s_sum[t] = v;
        __syncthreads();
    }
    unsigned incl = s_sum[t];                 // chunks t..255
    unsigned above = incl - sum;
    if ((int)above < K && K <= (int)incl) { s_chunk = t; s_krem = K - (int)above; }
    __syncthreads();
    int chunk = s_chunk, kRem = s_krem;
    if (t < 32) {                             // warp 0: refine within chunk
        unsigned c = s_bins[SWZ((chunk << 5) + t)];
        unsigned run = c;
        #pragma unroll
        for (int off = 1; off < 32; off <<= 1) {
            unsigned v = __shfl_down_sync(0xffffffffu, run, off);
            if (t + off < 32) run += v;
        }
        unsigned ab = run - c;                // bins above this one in chunk
        if ((int)ab < kRem && kRem <= (int)run)
            s_kth = (unsigned)((chunk << 5) + t) << BIN_SHIFT;
    }
    __syncthreads();
    return s_kth;
}

// one block: bitonic-sort candidates (value desc, idx asc), emit top K
__device__ void sort_emit(unsigned long long* s, unsigned long long* cand,
                          volatile int* cntp,
                          float* __restrict__ outV, float* __restrict__ outI, int K) {
    int cnt = *cntp;
    if (cnt > CAND_MAX) cnt = CAND_MAX;
    int n2 = 1; while (n2 < cnt) n2 <<= 1;
    for (int i = threadIdx.x; i < n2; i += 256)
        s[i] = (i < cnt) ? ((volatile unsigned long long*)cand)[i]
                         : 0xFFFFFFFFFFFFFFFFull;
    __syncthreads();
    for (int k = 2; k <= n2; k <<= 1) {
        for (int j = k >> 1; j > 0; j >>= 1) {
            for (int i = threadIdx.x; i < n2; i += 256) {
                int p = i ^ j;
                if (p > i) {
                    bool up = ((i & k) == 0);
                    unsigned long long a = s[i], b = s[p];
                    if ((a > b) == up) { s[i] = b; s[p] = a; }
                }
            }
            __syncthreads();
        }
    }
    for (int t = threadIdx.x; t < K; t += 256) {
        unsigned long long cc = s[t];
        outV[t] = keyf(~(unsigned)(cc >> 32));
        outI[t] = (float)(unsigned)(cc & 0xFFFFFFFFu);
    }
}

// ---------------- 1) projection: 128 thr, 8x4 tile + fused init/gumbel ------
// (R10-proven config: regs 85, occ 28.5%, 40us — frozen)
__global__ void __launch_bounds__(128)
k_proj(const float* __restrict__ emb, const float* __restrict__ W,
       const float* __restrict__ noise) {
    __shared__ float sE[64 * 68];
    __shared__ float sW[64 * 64];
    int tid = threadIdx.x;               // 128
    int base = blockIdx.x * 64 * DIM;
    int eb = blockIdx.x * 64;

    g_dd[2 * eb + tid] = 0.0f;
    if (tid < 64) g_sumnode[eb + tid] = 0.0f;
    if (blockIdx.x < 64)        g_bins_e[blockIdx.x * 128 + tid] = 0u;
    else if (blockIdx.x < 128)  g_bins_i[(blockIdx.x - 64) * 128 + tid] = 0u;
    else if (blockIdx.x == 128 && tid < 2) g_cnt[tid] = 0;

    const float4* ev = (const float4*)(emb + base);
    const float4* wv = (const float4*)W;
    #pragma unroll
    for (int i = tid; i < 1024; i += 128) {
        int r = i >> 4, c = i & 15;
        *(float4*)&sE[r * 68 + c * 4] = ev[i];
        ((float4*)sW)[i] = wv[i];
    }
    __syncthreads();

    // gumbel precompute: 1.5M edges over 400k threads, 4 coalesced strides
    {
        int t0 = blockIdx.x * 128 + tid;
        #pragma unroll
        for (int k = 0; k < 4; k++) {
            int e = t0 + k * 400000;
            if (e < NEDGE) g_gum[e] = __logf(neglog(__ldcs(&noise[e])));
        }
    }

    int tr = tid >> 4;
    int tc = tid & 15;

    unsigned long long a01[8], a23[8];
    #pragma unroll
    for (int i = 0; i < 8; i++) { a01[i] = 0ull; a23[i] = 0ull; }

    #pragma unroll
    for (int d4 = 0; d4 < 16; d4++) {
        unsigned long long w01[4], w23[4];
        #pragma unroll
        for (int j = 0; j < 4; j++) {
            float4 w = *(const float4*)&sW[(d4 * 4 + j) * 64 + tc * 4];
            PACK2(w01[j], w.x, w.y);
            PACK2(w23[j], w.z, w.w);
        }
        #pragma unroll
        for (int i = 0; i < 8; i++) {
            float4 e = *(const float4*)&sE[(tr * 8 + i) * 68 + d4 * 4];
            unsigned long long ee;
            PACK2(ee, e.x, e.x); FMA2(a01[i], ee, w01[0], a01[i]); FMA2(a23[i], ee, w23[0], a23[i]);
            PACK2(ee, e.y, e.y); FMA2(a01[i], ee, w01[1], a01[i]); FMA2(a23[i], ee, w23[1], a23[i]);
            PACK2(ee, e.z, e.z); FMA2(a01[i], ee, w01[2], a01[i]); FMA2(a23[i], ee, w23[2], a23[i]);
            PACK2(ee, e.w, e.w); FMA2(a01[i], ee, w01[3], a01[i]); FMA2(a23[i], ee, w23[3], a23[i]);
        }
    }
    #pragma unroll
    for (int i = 0; i < 8; i++) {
        float4 o;
        UNPACK2(o.x, o.y, a01[i]);
        UNPACK2(o.z, o.w, a23[i]);
        *(float4*)&g_proj[base + (tr * 8 + i) * 64 + tc * 4] = o;
    }
}

// ---------------- 2) edge kernel: 4 lanes/edge, 8 edges/warp, grid-stride ---
__device__ __forceinline__ void edge8(int grp,
                                      const int* __restrict__ head,
                                      const int* __restrict__ tail,
                                      const int* __restrict__ etype,
                                      const float* __restrict__ rel,
                                      int g, int sub) {
    int e = grp * 8 + g;
    int h = __ldcs(&head[e]);
    int t = __ldcs(&tail[e]);
    int r = __ldcs(&etype[e]) - 1;

    const float4* Q = (const float4*)&g_proj[(size_t)h << 6];
    const float4* K = (const float4*)&g_proj[(size_t)t << 6];
    const float4* R = (const float4*)rel + ((size_t)r << 4);

    float s = 0.0f;
    #pragma unroll
    for (int j = 0; j < 4; j++) {
        float4 q = __ldg(Q + sub + 4 * j);
        float4 k = __ldg(K + sub + 4 * j);
        float4 v = __ldg(R + sub + 4 * j);
        s += q.x * k.x * v.x + q.y * k.y * v.y + q.z * k.z * v.z + q.w * k.w * v.w;
    }
    s += __shfl_xor_sync(0xffffffffu, s, 1);
    s += __shfl_xor_sync(0xffffffffu, s, 2);

    float lg = s * SCALE;
    if (sub == 0) {
        float ex = __expf(lg);
        g_ex[e] = ex;
        atomicAdd(&g_dd[2 * h], ex);
    } else if (sub == 1) {
        atomicAdd(&g_dd[2 * h + 1], 1.0f);
    } else if (sub == 2) {
        atomicAdd(&g_sumnode[h], lg);
    } else {
        atomicAdd(&g_sumnode[t], lg);
    }
}

__global__ void __launch_bounds__(256)
k_edge(const int* __restrict__ head, const int* __restrict__ tail,
       const int* __restrict__ etype, const float* __restrict__ rel) {
    int warp = blockIdx.x * 8 + (threadIdx.x >> 5);
    int lane = threadIdx.x & 31;
    int g = lane >> 2;
    int sub = lane & 3;

    #pragma unroll 4
    for (int grp = warp; grp < EDGE_GROUPS; grp += EDGE_WARPS)
        edge8(grp, head, tail, etype, rel, g, sub);
}

// warp-aggregated smem histogram add
__device__ __forceinline__ void hist_add(unsigned* sh, unsigned bin) {
    unsigned m = __match_any_sync(0xffffffffu, bin);
    int leader = __ffs(m) - 1;
    if ((int)(threadIdx.x & 31) == leader) atomicAdd(&sh[bin], __popc(m));
}

// ---------------- 3) fused topk (edges + items), 2 grid syncs ---------------
__global__ void __launch_bounds__(256, 4)
k_topk(const int* __restrict__ head,
       float* __restrict__ out,
       float* __restrict__ tkv, float* __restrict__ tki,
       float* __restrict__ itv, float* __restrict__ iti) {
    __shared__ unsigned long long s_buf[NBINS / 2];   // 32KB: hist / select / sort
    unsigned* s_hist = (unsigned*)s_buf;
    unsigned key[2 * TE_PAIRS];
    int tid = threadIdx.x;
    bool isE = blockIdx.x < TE_BLOCKS;

    #pragma unroll
    for (int i = 0; i < NBINS / 256; i++) s_hist[tid + i * 256] = 0u;
    __syncthreads();

    // ---- phase A: pair-vectorized keys + warp-aggregated smem hist ----
    if (isE) {
        int gtid = blockIdx.x * 256 + tid;
        #pragma unroll
        for (int p = 0; p < TE_PAIRS; p++) {
            int pr = gtid + p * TE_STRIDE;            // pair index
            unsigned k0 = 0u, k1 = 0u;
            if (pr < NEDGE / 2) {
                int2  hh   = __ldcs((const int2*)head + pr);
                float2 ex2 = __ldcs((const float2*)g_ex + pr);
                float2 gm2 = __ldcs((const float2*)g_gum + pr);
                float2 d0  = *(const float2*)&g_dd[2 * hh.x];
                float2 d1  = *(const float2*)&g_dd[2 * hh.y];
                float sc0 = ex2.x * d0.y * __frcp_rn(d0.x);
                float sc1 = ex2.y * d1.y * __frcp_rn(d1.x);
                *(float2*)&out[2 * pr] = make_float2(sc0, sc1);
                k0 = fkey(sc0 - gm2.x);
                k1 = fkey(sc1 - gm2.y);
            }
            key[2 * p] = k0; key[2 * p + 1] = k1;
            hist_add(s_hist, k0 >> BIN_SHIFT);
            hist_add(s_hist, k1 >> BIN_SHIFT);
        }
        __syncthreads();
        #pragma unroll
        for (int i = 0; i < NBINS / 256; i++) {
            unsigned c = s_hist[tid + i * 256];
            if (c) atomicAdd(&g_bins_e[tid + i * 256], c);
        }
    } else {
        int gtid = (blockIdx.x - TE_BLOCKS) * 256 + tid;
        #pragma unroll
        for (int p = 0; p < TI_PAIRS; p++) {
            int pr = gtid + p * TI_STRIDE;
            unsigned k0 = 0u, k1 = 0u;
            if (pr < NI / 2) {
                float2 v = __ldcs((const float2*)g_sumnode + pr);
                k0 = fkey(v.x);
                k1 = fkey(v.y);
            }
            key[2 * p] = k0; key[2 * p + 1] = k1;
            hist_add(s_hist, k0 >> BIN_SHIFT);
            hist_add(s_hist, k1 >> BIN_SHIFT);
        }
        __syncthreads();
        #pragma unroll
        for (int i = 0; i < NBINS / 256; i++) {
            unsigned c = s_hist[tid + i * 256];
            if (c) atomicAdd(&g_bins_i[tid + i * 256], c);
        }
    }
    grid_sync();

    // ---- phase B: every block computes its threshold locally ----
    unsigned kth = isE ? select13s(g_bins_e, KEDGE, (unsigned*)s_buf)
                       : select13s(g_bins_i, KITEM, (unsigned*)s_buf);

    // ---- phase C: collect candidates >= threshold ----
    if (isE) {
        int gtid = blockIdx.x * 256 + tid;
        #pragma unroll
        for (int i = 0; i < 2 * TE_PAIRS; i++) {
            unsigned k = key[i];
            if (k >= kth) {
                int e = 2 * (gtid + (i >> 1) * TE_STRIDE) + (i & 1);
                int p = atomicAdd(&g_cnt[0], 1);
                if (p < CAND_MAX)
                    g_cand_e[p] = (((unsigned long long)(~k)) << 32) | (unsigned)e;
            }
        }
    } else {
        int gtid = (blockIdx.x - TE_BLOCKS) * 256 + tid;
        #pragma unroll
        for (int i = 0; i < 2 * TI_PAIRS; i++) {
            unsigned k = key[i];
            if (k >= kth) {
                int e = 2 * (gtid + (i >> 1) * TI_STRIDE) + (i & 1);
                int p = atomicAdd(&g_cnt[1], 1);
                if (p < CAND_MAX)
                    g_cand_i[p] = (((unsigned long long)(~k)) << 32) | (unsigned)e;
            }
        }
    }
    grid_sync();

    // ---- phase D: sort + emit ----
    if (blockIdx.x == 0)
        sort_emit(s_buf, g_cand_e, &g_cnt[0], tkv, tki, KEDGE);
    else if (blockIdx.x == TE_BLOCKS)
        sort_emit(s_buf, g_cand_i, &g_cnt[1], itv, iti, KITEM);
}

// ---------------- host ----------------
extern "C" void kernel_launch(void* const* d_in, const int* in_sizes, int n_in,
                              void* d_out, int out_size) {
    const float* emb   = (const float*)d_in[0];
    const float* WQ    = (const float*)d_in[1];
    const float* rel   = (const float*)d_in[2];
    const float* noise = (const float*)d_in[3];
    const int*   eidx  = (const int*)d_in[4];
    const int*   etype = (const int*)d_in[5];
    const int* head = eidx;
    const int* tail = eidx + NEDGE;
    float* out = (float*)d_out;

    float* out_tkv = out + NEDGE;
    float* out_tki = out + NEDGE + KEDGE;
    float* out_itv = out + NEDGE + 2 * KEDGE;
    float* out_iti = out + NEDGE + 2 * KEDGE + KITEM;

    k_proj<<<NE / 64, 128>>>(emb, WQ, noise);
    k_edge<<<EDGE_BLOCKS, 256>>>(head, tail, etype, rel);
    k_topk<<<NB_TOTAL, 256>>>(head, out, out_tkv, out_tki, out_itv, out_iti);
}

// round 16
// speedup vs baseline: 1.0155x; 1.0051x over previous
#include <cuda_runtime.h>
#include <math.h>

#define NE     200000
#define NI     100000
#define DIM    64
#define NEDGE  1500000
#define KEDGE  256
#define KITEM  100
#define SCALE  0.08838834764831845f   // 1/(2*sqrt(32))

#define CAND_MAX 2048
#define NBINS    8192                 // 13-bit key prefix
#define BIN_SHIFT 19

// topk persistent kernel: 592 blocks = 148 SM x 4 (co-resident)
#define TE_BLOCKS 512
#define TI_BLOCKS 80
#define NB_TOTAL  (TE_BLOCKS + TI_BLOCKS)
#define TE_STRIDE (TE_BLOCKS * 256)           // 131072 threads (edge part)
#define TE_PAIRS  6                           // 6 pairs = 12 edges/thread
#define TI_STRIDE (TI_BLOCKS * 256)           // 20480 threads (item part)
#define TI_PAIRS  3                           // 3 pairs = 6 items/thread

// edge kernel: grid-stride, 8 edges per warp per step (standalone: high occ)
#define EDGE_BLOCKS 1184                      // 148 * 8
#define EDGE_WARPS  (EDGE_BLOCKS * 8)         // 9472
#define EDGE_GROUPS (NEDGE / 8)               // 187500

// smem bank swizzle for the select stage (conflict-free both directions)
#define SWZ(x) ((x) ^ (((x) >> 5) & 31))

// ---------------- scratch ----------------
__device__ float    g_proj[NE * DIM];
__device__ float    g_ex[NEDGE];
__device__ float    g_gum[NEDGE];             // precomputed log(-log(u))
__device__ float    g_dd[2 * NE];             // [denom, deg] (8B-aligned pairs)
__device__ float    g_sumnode[NE];

__device__ unsigned g_bins_e[NBINS];
__device__ unsigned g_bins_i[NBINS];
__device__ int      g_cnt[2];
__device__ unsigned long long g_cand_e[CAND_MAX];
__device__ unsigned long long g_cand_i[CAND_MAX];

__device__ unsigned g_bar_cnt;                // zero-init, self-resetting
__device__ volatile unsigned g_bar_gen;

// ---------------- helpers ----------------
__device__ __forceinline__ unsigned fkey(float f) {
    unsigned u = __float_as_uint(f);
    return (u & 0x80000000u) ? ~u : (u | 0x80000000u);
}
__device__ __forceinline__ float keyf(unsigned k) {
    unsigned u = (k & 0x80000000u) ? (k & 0x7FFFFFFFu) : ~k;
    return __uint_as_float(u);
}

#define PACK2(out, lo, hi) \
    asm("mov.b64 %0, {%1, %2};" : "=l"(out) : "f"(lo), "f"(hi))
#define UNPACK2(lo, hi, in) \
    asm("mov.b64 {%0, %1}, %2;" : "=f"(lo), "=f"(hi) : "l"(in))
#define FMA2(d, a, b, c) \
    asm("fma.rn.f32x2 %0, %1, %2, %3;" : "=l"(d) : "l"(a), "l"(b), "l"(c))

// fused vector reduction: one REDG for (denom += ex, deg += 1)
#define RED_ADD_V2(ptr, a, b) \
    asm volatile("red.global.add.v2.f32 [%0], {%1, %2};" \
                 :: "l"(ptr), "f"(a), "f"(b) : "memory")

__device__ __forceinline__ void grid_sync() {
    __threadfence();
    __syncthreads();
    if (threadIdx.x == 0) {
        unsigned gen = g_bar_gen;
        if (atomicAdd(&g_bar_cnt, 1u) == gridDim.x - 1) {
            g_bar_cnt = 0u;
            __threadfence();
            g_bar_gen = gen + 1u;
        } else {
            while (g_bar_gen == gen) { __nanosleep(64); }
        }
        __threadfence();
    }
    __syncthreads();
}

// accurate-cheap -log(u): series near 1 (MUFU abs error would wreck the top
// gumbel candidates where x = -log u ~ 1e-6), __logf elsewhere
__device__ __forceinline__ float neglog(float u) {
    float t = u - 1.0f;
    float p = fmaf(t, -0.16666667f, 0.2f);
    p = fmaf(t, p, -0.25f);
    p = fmaf(t, p, 0.33333333f);
    p = fmaf(t, p, -0.5f);
    p = fmaf(t, p, 1.0f);
    float ser = -t * p;
    float fast = -__logf(u);
    return (u > 0.84f) ? ser : fast;
}

// every block runs this (deterministic -> same answer everywhere).
// bins staged coalesced into swizzled smem, then 2-level suffix select.
__device__ unsigned select13s(const unsigned* bins, int K, unsigned* s_bins) {
    __shared__ unsigned s_sum[256];
    __shared__ int s_chunk, s_krem;
    __shared__ unsigned s_kth;
    int t = threadIdx.x;
    #pragma unroll
    for (int i = 0; i < 32; i++) {
        int L = i * 256 + t;                  // coalesced L2 read
        s_bins[SWZ(L)] = __ldcg(&bins[L]);
    }
    __syncthreads();
    unsigned sum = 0;
    #pragma unroll
    for (int i = 0; i < 32; i++) sum += s_bins[SWZ(t * 32 + i)];   // conflict-free
    s_sum[t] = sum;
    __syncthreads();
    #pragma unroll
    for (int off = 1; off < 256; off <<= 1) {
        unsigned v = s_sum[t];
        if (t + off < 256) v += s_sum[t + off];
        __syncthreads();
        s_sum[t] = v;
        __syncthreads();
    }
    unsigned incl = s_sum[t];                 // chunks t..255
    unsigned above = incl - sum;
    if ((int)above < K && K <= (int)incl) { s_chunk = t; s_krem = K - (int)above; }
    __syncthreads();
    int chunk = s_chunk, kRem = s_krem;
    if (t < 32) {                             // warp 0: refine within chunk
        unsigned c = s_bins[SWZ((chunk << 5) + t)];
        unsigned run = c;
        #pragma unroll
        for (int off = 1; off < 32; off <<= 1) {
            unsigned v = __shfl_down_sync(0xffffffffu, run, off);
            if (t + off < 32) run += v;
        }
        unsigned ab = run - c;                // bins above this one in chunk
        if ((int)ab < kRem && kRem <= (int)run)
            s_kth = (unsigned)((chunk << 5) + t) << BIN_SHIFT;
    }
    __syncthreads();
    return s_kth;
}

// one block: bitonic-sort candidates (value desc, idx asc), emit top K
__device__ void sort_emit(unsigned long long* s, unsigned long long* cand,
                          volatile int* cntp,
                          float* __restrict__ outV, float* __restrict__ outI, int K) {
    int cnt = *cntp;
    if (cnt > CAND_MAX) cnt = CAND_MAX;
    int n2 = 1; while (n2 < cnt) n2 <<= 1;
    for (int i = threadIdx.x; i < n2; i += 256)
        s[i] = (i < cnt) ? ((volatile unsigned long long*)cand)[i]
                         : 0xFFFFFFFFFFFFFFFFull;
    __syncthreads();
    for (int k = 2; k <= n2; k <<= 1) {
        for (int j = k >> 1; j > 0; j >>= 1) {
            for (int i = threadIdx.x; i < n2; i += 256) {
                int p = i ^ j;
                if (p > i) {
                    bool up = ((i & k) == 0);
                    unsigned long long a = s[i], b = s[p];
                    if ((a > b) == up) { s[i] = b; s[p] = a; }
                }
            }
            __syncthreads();
        }
    }
    for (int t = threadIdx.x; t < K; t += 256) {
        unsigned long long cc = s[t];
        outV[t] = keyf(~(unsigned)(cc >> 32));
        outI[t] = (float)(unsigned)(cc & 0xFFFFFFFFu);
    }
}

// ---------------- 1) projection: 128 thr, 8x4 tile + fused init/gumbel ------
// (R10-proven config: regs 85, occ 28.5%, 40us — frozen)
__global__ void __launch_bounds__(128)
k_proj(const float* __restrict__ emb, const float* __restrict__ W,
       const float* __restrict__ noise) {
    __shared__ float sE[64 * 68];
    __shared__ float sW[64 * 64];
    int tid = threadIdx.x;               // 128
    int base = blockIdx.x * 64 * DIM;
    int eb = blockIdx.x * 64;

    g_dd[2 * eb + tid] = 0.0f;
    if (tid < 64) g_sumnode[eb + tid] = 0.0f;
    if (blockIdx.x < 64)        g_bins_e[blockIdx.x * 128 + tid] = 0u;
    else if (blockIdx.x < 128)  g_bins_i[(blockIdx.x - 64) * 128 + tid] = 0u;
    else if (blockIdx.x == 128 && tid < 2) g_cnt[tid] = 0;

    const float4* ev = (const float4*)(emb + base);
    const float4* wv = (const float4*)W;
    #pragma unroll
    for (int i = tid; i < 1024; i += 128) {
        int r = i >> 4, c = i & 15;
        *(float4*)&sE[r * 68 + c * 4] = ev[i];
        ((float4*)sW)[i] = wv[i];
    }
    __syncthreads();

    // gumbel precompute: 1.5M edges over 400k threads, 4 coalesced strides
    {
        int t0 = blockIdx.x * 128 + tid;
        #pragma unroll
        for (int k = 0; k < 4; k++) {
            int e = t0 + k * 400000;
            if (e < NEDGE) g_gum[e] = __logf(neglog(__ldcs(&noise[e])));
        }
    }

    int tr = tid >> 4;
    int tc = tid & 15;

    unsigned long long a01[8], a23[8];
    #pragma unroll
    for (int i = 0; i < 8; i++) { a01[i] = 0ull; a23[i] = 0ull; }

    #pragma unroll
    for (int d4 = 0; d4 < 16; d4++) {
        unsigned long long w01[4], w23[4];
        #pragma unroll
        for (int j = 0; j < 4; j++) {
            float4 w = *(const float4*)&sW[(d4 * 4 + j) * 64 + tc * 4];
            PACK2(w01[j], w.x, w.y);
            PACK2(w23[j], w.z, w.w);
        }
        #pragma unroll
        for (int i = 0; i < 8; i++) {
            float4 e = *(const float4*)&sE[(tr * 8 + i) * 68 + d4 * 4];
            unsigned long long ee;
            PACK2(ee, e.x, e.x); FMA2(a01[i], ee, w01[0], a01[i]); FMA2(a23[i], ee, w23[0], a23[i]);
            PACK2(ee, e.y, e.y); FMA2(a01[i], ee, w01[1], a01[i]); FMA2(a23[i], ee, w23[1], a23[i]);
            PACK2(ee, e.z, e.z); FMA2(a01[i], ee, w01[2], a01[i]); FMA2(a23[i], ee, w23[2], a23[i]);
            PACK2(ee, e.w, e.w); FMA2(a01[i], ee, w01[3], a01[i]); FMA2(a23[i], ee, w23[3], a23[i]);
        }
    }
    #pragma unroll
    for (int i = 0; i < 8; i++) {
        float4 o;
        UNPACK2(o.x, o.y, a01[i]);
        UNPACK2(o.z, o.w, a23[i]);
        *(float4*)&g_proj[base + (tr * 8 + i) * 64 + tc * 4] = o;
    }
}

// ---------------- 2) edge kernel: 4 lanes/edge, 8 edges/warp, grid-stride ---
__device__ __forceinline__ void edge8(int grp,
                                      const int* __restrict__ head,
                                      const int* __restrict__ tail,
                                      const int* __restrict__ etype,
                                      const float* __restrict__ rel,
                                      int g, int sub) {
    int e = grp * 8 + g;
    int h = __ldcs(&head[e]);
    int t = __ldcs(&tail[e]);
    int r = __ldcs(&etype[e]) - 1;

    const float4* Q = (const float4*)&g_proj[(size_t)h << 6];
    const float4* K = (const float4*)&g_proj[(size_t)t << 6];
    const float4* R = (const float4*)rel + ((size_t)r << 4);

    float s = 0.0f;
    #pragma unroll
    for (int j = 0; j < 4; j++) {
        float4 q = __ldg(Q + sub + 4 * j);
        float4 k = __ldg(K + sub + 4 * j);
        float4 v = __ldg(R + sub + 4 * j);
        s += q.x * k.x * v.x + q.y * k.y * v.y + q.z * k.z * v.z + q.w * k.w * v.w;
    }
    s += __shfl_xor_sync(0xffffffffu, s, 1);
    s += __shfl_xor_sync(0xffffffffu, s, 2);

    float lg = s * SCALE;
    if (sub == 0) {
        float ex = __expf(lg);
        g_ex[e] = ex;
        RED_ADD_V2(&g_dd[2 * h], ex, 1.0f);   // denom += ex, deg += 1 (one REDG)
    } else if (sub == 1) {
        atomicAdd(&g_sumnode[h], lg);
    } else if (sub == 2) {
        atomicAdd(&g_sumnode[t], lg);
    }
}

__global__ void __launch_bounds__(256)
k_edge(const int* __restrict__ head, const int* __restrict__ tail,
       const int* __restrict__ etype, const float* __restrict__ rel) {
    int warp = blockIdx.x * 8 + (threadIdx.x >> 5);
    int lane = threadIdx.x & 31;
    int g = lane >> 2;
    int sub = lane & 3;

    #pragma unroll 4
    for (int grp = warp; grp < EDGE_GROUPS; grp += EDGE_WARPS)
        edge8(grp, head, tail, etype, rel, g, sub);
}

// warp-aggregated smem histogram add
__device__ __forceinline__ void hist_add(unsigned* sh, unsigned bin) {
    unsigned m = __match_any_sync(0xffffffffu, bin);
    int leader = __ffs(m) - 1;
    if ((int)(threadIdx.x & 31) == leader) atomicAdd(&sh[bin], __popc(m));
}

// ---------------- 3) fused topk (edges + items), 2 grid syncs ---------------
__global__ void __launch_bounds__(256, 4)
k_topk(const int* __restrict__ head,
       float* __restrict__ out,
       float* __restrict__ tkv, float* __restrict__ tki,
       float* __restrict__ itv, float* __restrict__ iti) {
    __shared__ unsigned long long s_buf[NBINS / 2];   // 32KB: hist / select / sort
    unsigned* s_hist = (unsigned*)s_buf;
    unsigned key[2 * TE_PAIRS];
    int tid = threadIdx.x;
    bool isE = blockIdx.x < TE_BLOCKS;

    #pragma unroll
    for (int i = 0; i < NBINS / 256; i++) s_hist[tid + i * 256] = 0u;
    __syncthreads();

    // ---- phase A: pair-vectorized keys + warp-aggregated smem hist ----
    if (isE) {
        int gtid = blockIdx.x * 256 + tid;
        #pragma unroll
        for (int p = 0; p < TE_PAIRS; p++) {
            int pr = gtid + p * TE_STRIDE;            // pair index
            unsigned k0 = 0u, k1 = 0u;
            if (pr < NEDGE / 2) {
                int2  hh   = __ldcs((const int2*)head + pr);
                float2 ex2 = __ldcs((const float2*)g_ex + pr);
                float2 gm2 = __ldcs((const float2*)g_gum + pr);
                float2 d0  = *(const float2*)&g_dd[2 * hh.x];
                float2 d1  = *(const float2*)&g_dd[2 * hh.y];
                float sc0 = ex2.x * d0.y * __frcp_rn(d0.x);
                float sc1 = ex2.y * d1.y * __frcp_rn(d1.x);
                *(float2*)&out[2 * pr] = make_float2(sc0, sc1);
                k0 = fkey(sc0 - gm2.x);
                k1 = fkey(sc1 - gm2.y);
            }
            key[2 * p] = k0; key[2 * p + 1] = k1;
            hist_add(s_hist, k0 >> BIN_SHIFT);
            hist_add(s_hist, k1 >> BIN_SHIFT);
        }
        __syncthreads();
        #pragma unroll
        for (int i = 0; i < NBINS / 256; i++) {
            unsigned c = s_hist[tid + i * 256];
            if (c) atomicAdd(&g_bins_e[tid + i * 256], c);
        }
    } else {
        int gtid = (blockIdx.x - TE_BLOCKS) * 256 + tid;
        #pragma unroll
        for (int p = 0; p < TI_PAIRS; p++) {
            int pr = gtid + p * TI_STRIDE;
            unsigned k0 = 0u, k1 = 0u;
            if (pr < NI / 2) {
                float2 v = __ldcs((const float2*)g_sumnode + pr);
                k0 = fkey(v.x);
                k1 = fkey(v.y);
            }
            key[2 * p] = k0; key[2 * p + 1] = k1;
            hist_add(s_hist, k0 >> BIN_SHIFT);
            hist_add(s_hist, k1 >> BIN_SHIFT);
        }
        __syncthreads();
        #pragma unroll
        for (int i = 0; i < NBINS / 256; i++) {
            unsigned c = s_hist[tid + i * 256];
            if (c) atomicAdd(&g_bins_i[tid + i * 256], c);
        }
    }
    grid_sync();

    // ---- phase B: every block computes its threshold locally ----
    unsigned kth = isE ? select13s(g_bins_e, KEDGE, (unsigned*)s_buf)
                       : select13s(g_bins_i, KITEM, (unsigned*)s_buf);

    // ---- phase C: collect candidates >= threshold ----
    if (isE) {
        int gtid = blockIdx.x * 256 + tid;
        #pragma unroll
        for (int i = 0; i < 2 * TE_PAIRS; i++) {
            unsigned k = key[i];
            if (k >= kth) {
                int e = 2 * (gtid + (i >> 1) * TE_STRIDE) + (i & 1);
                int p = atomicAdd(&g_cnt[0], 1);
                if (p < CAND_MAX)
                    g_cand_e[p] = (((unsigned long long)(~k)) << 32) | (unsigned)e;
            }
        }
    } else {
        int gtid = (blockIdx.x - TE_BLOCKS) * 256 + tid;
        #pragma unroll
        for (int i = 0; i < 2 * TI_PAIRS; i++) {
            unsigned k = key[i];
            if (k >= kth) {
                int e = 2 * (gtid + (i >> 1) * TI_STRIDE) + (i & 1);
                int p = atomicAdd(&g_cnt[1], 1);
                if (p < CAND_MAX)
                    g_cand_i[p] = (((unsigned long long)(~k)) << 32) | (unsigned)e;
            }
        }
    }
    grid_sync();

    // ---- phase D: sort + emit ----
    if (blockIdx.x == 0)
        sort_emit(s_buf, g_cand_e, &g_cnt[0], tkv, tki, KEDGE);
    else if (blockIdx.x == TE_BLOCKS)
        sort_emit(s_buf, g_cand_i, &g_cnt[1], itv, iti, KITEM);
}

// ---------------- host ----------------
extern "C" void kernel_launch(void* const* d_in, const int* in_sizes, int n_in,
                              void* d_out, int out_size) {
    const float* emb   = (const float*)d_in[0];
    const float* WQ    = (const float*)d_in[1];
    const float* rel   = (const float*)d_in[2];
    const float* noise = (const float*)d_in[3];
    const int*   eidx  = (const int*)d_in[4];
    const int*   etype = (const int*)d_in[5];
    const int* head = eidx;
    const int* tail = eidx + NEDGE;
    float* out = (float*)d_out;

    float* out_tkv = out + NEDGE;
    float* out_tki = out + NEDGE + KEDGE;
    float* out_itv = out + NEDGE + 2 * KEDGE;
    float* out_iti = out + NEDGE + 2 * KEDGE + KITEM;

    k_proj<<<NE / 64, 128>>>(emb, WQ, noise);
    k_edge<<<EDGE_BLOCKS, 256>>>(head, tail, etype, rel);
    k_topk<<<NB_TOTAL, 256>>>(head, out, out_tkv, out_tki, out_itv, out_iti);
}

// round 17
// speedup vs baseline: 1.0225x; 1.0069x over previous
#include <cuda_runtime.h>
#include <math.h>

#define NE     200000
#define NI     100000
#define DIM    64
#define NEDGE  1500000
#define KEDGE  256
#define KITEM  100
#define SCALE  0.08838834764831845f   // 1/(2*sqrt(32))

#define CAND_MAX 2048
#define NBINS    8192                 // 13-bit key prefix
#define BIN_SHIFT 19

// topk persistent kernel: 592 blocks = 148 SM x 4 (co-resident)
#define TE_BLOCKS 512
#define TI_BLOCKS 80
#define NB_TOTAL  (TE_BLOCKS + TI_BLOCKS)
#define TE_STRIDE (TE_BLOCKS * 256)           // 131072 threads (edge part)
#define TE_PAIRS  6                           // 6 pairs = 12 edges/thread
#define TI_STRIDE (TI_BLOCKS * 256)           // 20480 threads (item part)
#define TI_PAIRS  3                           // 3 pairs = 6 items/thread

// edge kernel: grid-stride, 8 edges per warp per step (standalone: high occ)
#define EDGE_BLOCKS 1184                      // 148 * 8
#define EDGE_WARPS  (EDGE_BLOCKS * 8)         // 9472
#define EDGE_GROUPS (NEDGE / 8)               // 187500

// smem bank swizzle for the select stage (conflict-free both directions)
#define SWZ(x) ((x) ^ (((x) >> 5) & 31))

// ---------------- scratch ----------------
__device__ float    g_proj[NE * DIM];
__device__ float    g_ex[NEDGE];
__device__ float    g_gum[NEDGE];             // precomputed log(-log(u))
__device__ float    g_dd[2 * NE];             // [denom, deg] (8B-aligned pairs)
__device__ float    g_sumnode[NE];

__device__ unsigned g_bins_e[NBINS];
__device__ unsigned g_bins_i[NBINS];
__device__ int      g_cnt[2];
__device__ unsigned long long g_cand_e[CAND_MAX];
__device__ unsigned long long g_cand_i[CAND_MAX];

__device__ unsigned g_bar_cnt;                // zero-init, self-resetting
__device__ volatile unsigned g_bar_gen;

// ---------------- helpers ----------------
__device__ __forceinline__ unsigned fkey(float f) {
    unsigned u = __float_as_uint(f);
    return (u & 0x80000000u) ? ~u : (u | 0x80000000u);
}
__device__ __forceinline__ float keyf(unsigned k) {
    unsigned u = (k & 0x80000000u) ? (k & 0x7FFFFFFFu) : ~k;
    return __uint_as_float(u);
}

#define PACK2(out, lo, hi) \
    asm("mov.b64 %0, {%1, %2};" : "=l"(out) : "f"(lo), "f"(hi))
#define UNPACK2(lo, hi, in) \
    asm("mov.b64 {%0, %1}, %2;" : "=f"(lo), "=f"(hi) : "l"(in))
#define FMA2(d, a, b, c) \
    asm("fma.rn.f32x2 %0, %1, %2, %3;" : "=l"(d) : "l"(a), "l"(b), "l"(c))

// fused vector reduction: one REDG for (denom += ex, deg += 1)
#define RED_ADD_V2(ptr, a, b) \
    asm volatile("red.global.add.v2.f32 [%0], {%1, %2};" \
                 :: "l"(ptr), "f"(a), "f"(b) : "memory")

__device__ __forceinline__ void grid_sync() {
    __threadfence();
    __syncthreads();
    if (threadIdx.x == 0) {
        unsigned gen = g_bar_gen;
        if (atomicAdd(&g_bar_cnt, 1u) == gridDim.x - 1) {
            g_bar_cnt = 0u;
            __threadfence();
            g_bar_gen = gen + 1u;
        } else {
            while (g_bar_gen == gen) { __nanosleep(64); }
        }
        __threadfence();
    }
    __syncthreads();
}

// accurate-cheap -log(u): series near 1 (MUFU abs error would wreck the top
// gumbel candidates where x = -log u ~ 1e-6), __logf elsewhere
__device__ __forceinline__ float neglog(float u) {
    float t = u - 1.0f;
    float p = fmaf(t, -0.16666667f, 0.2f);
    p = fmaf(t, p, -0.25f);
    p = fmaf(t, p, 0.33333333f);
    p = fmaf(t, p, -0.5f);
    p = fmaf(t, p, 1.0f);
    float ser = -t * p;
    float fast = -__logf(u);
    return (u > 0.84f) ? ser : fast;
}

// every block runs this (deterministic -> same answer everywhere).
// bins staged coalesced into swizzled smem, then 2-level suffix select.
__device__ unsigned select13s(const unsigned* bins, int K, unsigned* s_bins) {
    __shared__ unsigned s_sum[256];
    __shared__ int s_chunk, s_krem;
    __shared__ unsigned s_kth;
    int t = threadIdx.x;
    #pragma unroll
    for (int i = 0; i < 32; i++) {
        int L = i * 256 + t;                  // coalesced L2 read
        s_bins[SWZ(L)] = __ldcg(&bins[L]);
    }
    __syncthreads();
    unsigned sum = 0;
    #pragma unroll
    for (int i = 0; i < 32; i++) sum += s_bins[SWZ(t * 32 + i)];   // conflict-free
    s_sum[t] = sum;
    __syncthreads();
    #pragma unroll
    for (int off = 1; off < 256; off <<= 1) {
        unsigned v = s_sum[t];
        if (t + off < 256) v += s_sum[t + off];
        __syncthreads();
        s_sum[t] = v;
        __syncthreads();
    }
    unsigned incl = s_sum[t];                 // chunks t..255
    unsigned above = incl - sum;
    if ((int)above < K && K <= (int)incl) { s_chunk = t; s_krem = K - (int)above; }
    __syncthreads();
    int chunk = s_chunk, kRem = s_krem;
    if (t < 32) {                             // warp 0: refine within chunk
        unsigned c = s_bins[SWZ((chunk << 5) + t)];
        unsigned run = c;
        #pragma unroll
        for (int off = 1; off < 32; off <<= 1) {
            unsigned v = __shfl_down_sync(0xffffffffu, run, off);
            if (t + off < 32) run += v;
        }
        unsigned ab = run - c;                // bins above this one in chunk
        if ((int)ab < kRem && kRem <= (int)run)
            s_kth = (unsigned)((chunk << 5) + t) << BIN_SHIFT;
    }
    __syncthreads();
    return s_kth;
}

// one block: bitonic-sort candidates (value desc, idx asc), emit top K
__device__ void sort_emit(unsigned long long* s, unsigned long long* cand,
                          volatile int* cntp,
                          float* __restrict__ outV, float* __restrict__ outI, int K) {
    int cnt = *cntp;
    if (cnt > CAND_MAX) cnt = CAND_MAX;
    int n2 = 1; while (n2 < cnt) n2 <<= 1;
    for (int i = threadIdx.x; i < n2; i += 256)
        s[i] = (i < cnt) ? ((volatile unsigned long long*)cand)[i]
                         : 0xFFFFFFFFFFFFFFFFull;
    __syncthreads();
    for (int k = 2; k <= n2; k <<= 1) {
        for (int j = k >> 1; j > 0; j >>= 1) {
            for (int i = threadIdx.x; i < n2; i += 256) {
                int p = i ^ j;
                if (p > i) {
                    bool up = ((i & k) == 0);
                    unsigned long long a = s[i], b = s[p];
                    if ((a > b) == up) { s[i] = b; s[p] = a; }
                }
            }
            __syncthreads();
        }
    }
    for (int t = threadIdx.x; t < K; t += 256) {
        unsigned long long cc = s[t];
        outV[t] = keyf(~(unsigned)(cc >> 32));
        outI[t] = (float)(unsigned)(cc & 0xFFFFFFFFu);
    }
}

// ---------------- 1) projection: 128 thr, 8x4 tile + fused init/gumbel ------
// (R10-proven config: regs 85, occ 28.5%, 40us — frozen)
__global__ void __launch_bounds__(128)
k_proj(const float* __restrict__ emb, const float* __restrict__ W,
       const float* __restrict__ noise) {
    __shared__ float sE[64 * 68];
    __shared__ float sW[64 * 64];
    int tid = threadIdx.x;               // 128
    int base = blockIdx.x * 64 * DIM;
    int eb = blockIdx.x * 64;

    g_dd[2 * eb + tid] = 0.0f;
    if (tid < 64) g_sumnode[eb + tid] = 0.0f;
    if (blockIdx.x < 64)        g_bins_e[blockIdx.x * 128 + tid] = 0u;
    else if (blockIdx.x < 128)  g_bins_i[(blockIdx.x - 64) * 128 + tid] = 0u;
    else if (blockIdx.x == 128 && tid < 2) g_cnt[tid] = 0;

    const float4* ev = (const float4*)(emb + base);
    const float4* wv = (const float4*)W;
    #pragma unroll
    for (int i = tid; i < 1024; i += 128) {
        int r = i >> 4, c = i & 15;
        *(float4*)&sE[r * 68 + c * 4] = ev[i];
        ((float4*)sW)[i] = wv[i];
    }
    __syncthreads();

    // gumbel precompute: 1.5M edges over 400k threads, 4 coalesced strides
    {
        int t0 = blockIdx.x * 128 + tid;
        #pragma unroll
        for (int k = 0; k < 4; k++) {
            int e = t0 + k * 400000;
            if (e < NEDGE) g_gum[e] = __logf(neglog(__ldg(&noise[e])));
        }
    }

    int tr = tid >> 4;
    int tc = tid & 15;

    unsigned long long a01[8], a23[8];
    #pragma unroll
    for (int i = 0; i < 8; i++) { a01[i] = 0ull; a23[i] = 0ull; }

    #pragma unroll
    for (int d4 = 0; d4 < 16; d4++) {
        unsigned long long w01[4], w23[4];
        #pragma unroll
        for (int j = 0; j < 4; j++) {
            float4 w = *(const float4*)&sW[(d4 * 4 + j) * 64 + tc * 4];
            PACK2(w01[j], w.x, w.y);
            PACK2(w23[j], w.z, w.w);
        }
        #pragma unroll
        for (int i = 0; i < 8; i++) {
            float4 e = *(const float4*)&sE[(tr * 8 + i) * 68 + d4 * 4];
            unsigned long long ee;
            PACK2(ee, e.x, e.x); FMA2(a01[i], ee, w01[0], a01[i]); FMA2(a23[i], ee, w23[0], a23[i]);
            PACK2(ee, e.y, e.y); FMA2(a01[i], ee, w01[1], a01[i]); FMA2(a23[i], ee, w23[1], a23[i]);
            PACK2(ee, e.z, e.z); FMA2(a01[i], ee, w01[2], a01[i]); FMA2(a23[i], ee, w23[2], a23[i]);
            PACK2(ee, e.w, e.w); FMA2(a01[i], ee, w01[3], a01[i]); FMA2(a23[i], ee, w23[3], a23[i]);
        }
    }
    #pragma unroll
    for (int i = 0; i < 8; i++) {
        float4 o;
        UNPACK2(o.x, o.y, a01[i]);
        UNPACK2(o.z, o.w, a23[i]);
        *(float4*)&g_proj[base + (tr * 8 + i) * 64 + tc * 4] = o;
    }
}

// ---------------- 2) edge kernel: 4 lanes/edge, 8 edges/warp, grid-stride ---
__device__ __forceinline__ void edge8(int grp,
                                      const int* __restrict__ head,
                                      const int* __restrict__ tail,
                                      const int* __restrict__ etype,
                                      const float* __restrict__ rel,
                                      int g, int sub) {
    int e = grp * 8 + g;
    int h = __ldg(&head[e]);
    int t = __ldg(&tail[e]);
    int r = __ldg(&etype[e]) - 1;

    const float4* Q = (const float4*)&g_proj[(size_t)h << 6];
    const float4* K = (const float4*)&g_proj[(size_t)t << 6];
    const float4* R = (const float4*)rel + ((size_t)r << 4);

    float s = 0.0f;
    #pragma unroll
    for (int j = 0; j < 4; j++) {
        float4 q = __ldg(Q + sub + 4 * j);
        float4 k = __ldg(K + sub + 4 * j);
        float4 v = __ldg(R + sub + 4 * j);
        s += q.x * k.x * v.x + q.y * k.y * v.y + q.z * k.z * v.z + q.w * k.w * v.w;
    }
    s += __shfl_xor_sync(0xffffffffu, s, 1);
    s += __shfl_xor_sync(0xffffffffu, s, 2);

    float lg = s * SCALE;
    if (sub == 0) {
        float ex = __expf(lg);
        g_ex[e] = ex;
        RED_ADD_V2(&g_dd[2 * h], ex, 1.0f);   // denom += ex, deg += 1 (one REDG)
    } else if (sub == 1) {
        atomicAdd(&g_sumnode[h], lg);
    } else if (sub == 2) {
        atomicAdd(&g_sumnode[t], lg);
    }
}

__global__ void __launch_bounds__(256)
k_edge(const int* __restrict__ head, const int* __restrict__ tail,
       const int* __restrict__ etype, const float* __restrict__ rel) {
    int warp = blockIdx.x * 8 + (threadIdx.x >> 5);
    int lane = threadIdx.x & 31;
    int g = lane >> 2;
    int sub = lane & 3;

    int grp = warp;
    #pragma unroll 2
    for (; grp + EDGE_WARPS < EDGE_GROUPS; grp += EDGE_WARPS)
        edge8(grp, head, tail, etype, rel, g, sub);
    if (grp < EDGE_GROUPS)
        edge8(grp, head, tail, etype, rel, g, sub);
}

// warp-aggregated smem histogram add
__device__ __forceinline__ void hist_add(unsigned* sh, unsigned bin) {
    unsigned m = __match_any_sync(0xffffffffu, bin);
    int leader = __ffs(m) - 1;
    if ((int)(threadIdx.x & 31) == leader) atomicAdd(&sh[bin], __popc(m));
}

// ---------------- 3) fused topk (edges + items), 2 grid syncs ---------------
__global__ void __launch_bounds__(256, 4)
k_topk(const int* __restrict__ head,
       float* __restrict__ out,
       float* __restrict__ tkv, float* __restrict__ tki,
       float* __restrict__ itv, float* __restrict__ iti) {
    __shared__ unsigned long long s_buf[NBINS / 2];   // 32KB: hist / select / sort
    unsigned* s_hist = (unsigned*)s_buf;
    unsigned key[2 * TE_PAIRS];
    int tid = threadIdx.x;
    bool isE = blockIdx.x < TE_BLOCKS;

    #pragma unroll
    for (int i = 0; i < NBINS / 256; i++) s_hist[tid + i * 256] = 0u;
    __syncthreads();

    // ---- phase A: pair-vectorized keys + warp-aggregated smem hist ----
    if (isE) {
        int gtid = blockIdx.x * 256 + tid;
        #pragma unroll
        for (int p = 0; p < TE_PAIRS; p++) {
            int pr = gtid + p * TE_STRIDE;            // pair index
            unsigned k0 = 0u, k1 = 0u;
            if (pr < NEDGE / 2) {
                int2  hh   = __ldg((const int2*)head + pr);
                float2 ex2 = __ldg((const float2*)g_ex + pr);
                float2 gm2 = __ldg((const float2*)g_gum + pr);
                float2 d0  = *(const float2*)&g_dd[2 * hh.x];
                float2 d1  = *(const float2*)&g_dd[2 * hh.y];
                float sc0 = ex2.x * d0.y * __frcp_rn(d0.x);
                float sc1 = ex2.y * d1.y * __frcp_rn(d1.x);
                *(float2*)&out[2 * pr] = make_float2(sc0, sc1);
                k0 = fkey(sc0 - gm2.x);
                k1 = fkey(sc1 - gm2.y);
            }
            key[2 * p] = k0; key[2 * p + 1] = k1;
            hist_add(s_hist, k0 >> BIN_SHIFT);
            hist_add(s_hist, k1 >> BIN_SHIFT);
        }
        __syncthreads();
        #pragma unroll
        for (int i = 0; i < NBINS / 256; i++) {
            unsigned c = s_hist[tid + i * 256];
            if (c) atomicAdd(&g_bins_e[tid + i * 256], c);
        }
    } else {
        int gtid = (blockIdx.x - TE_BLOCKS) * 256 + tid;
        #pragma unroll
        for (int p = 0; p < TI_PAIRS; p++) {
            int pr = gtid + p * TI_STRIDE;
            unsigned k0 = 0u, k1 = 0u;
            if (pr < NI / 2) {
                float2 v = __ldg((const float2*)g_sumnode + pr);
                k0 = fkey(v.x);
                k1 = fkey(v.y);
            }
            key[2 * p] = k0; key[2 * p + 1] = k1;
            hist_add(s_hist, k0 >> BIN_SHIFT);
            hist_add(s_hist, k1 >> BIN_SHIFT);
        }
        __syncthreads();
        #pragma unroll
        for (int i = 0; i < NBINS / 256; i++) {
            unsigned c = s_hist[tid + i * 256];
            if (c) atomicAdd(&g_bins_i[tid + i * 256], c);
        }
    }
    grid_sync();

    // ---- phase B: every block computes its threshold locally ----
    unsigned kth = isE ? select13s(g_bins_e, KEDGE, (unsigned*)s_buf)
                       : select13s(g_bins_i, KITEM, (unsigned*)s_buf);

    // ---- phase C: collect candidates >= threshold ----
    if (isE) {
        int gtid = blockIdx.x * 256 + tid;
        #pragma unroll
        for (int i = 0; i < 2 * TE_PAIRS; i++) {
            unsigned k = key[i];
            if (k >= kth) {
                int e = 2 * (gtid + (i >> 1) * TE_STRIDE) + (i & 1);
                int p = atomicAdd(&g_cnt[0], 1);
                if (p < CAND_MAX)
                    g_cand_e[p] = (((unsigned long long)(~k)) << 32) | (unsigned)e;
            }
        }
    } else {
        int gtid = (blockIdx.x - TE_BLOCKS) * 256 + tid;
        #pragma unroll
        for (int i = 0; i < 2 * TI_PAIRS; i++) {
            unsigned k = key[i];
            if (k >= kth) {
                int e = 2 * (gtid + (i >> 1) * TI_STRIDE) + (i & 1);
                int p = atomicAdd(&g_cnt[1], 1);
                if (p < CAND_MAX)
                    g_cand_i[p] = (((unsigned long long)(~k)) << 32) | (unsigned)e;
            }
        }
    }
    grid_sync();

    // ---- phase D: sort + emit ----
    if (blockIdx.x == 0)
        sort_emit(s_buf, g_cand_e, &g_cnt[0], tkv, tki, KEDGE);
    else if (blockIdx.x == TE_BLOCKS)
        sort_emit(s_buf, g_cand_i, &g_cnt[1], itv, iti, KITEM);
}

// ---------------- host ----------------
extern "C" void kernel_launch(void* const* d_in, const int* in_sizes, int n_in,
                              void* d_out, int out_size) {
    const float* emb   = (const float*)d_in[0];
    const float* WQ    = (const float*)d_in[1];
    const float* rel   = (const float*)d_in[2];
    const float* noise = (const float*)d_in[3];
    const int*   eidx  = (const int*)d_in[4];
    const int*   etype = (const int*)d_in[5];
    const int* head = eidx;
    const int* tail = eidx + NEDGE;
    float* out = (float*)d_out;

    float* out_tkv = out + NEDGE;
    float* out_tki = out + NEDGE + KEDGE;
    float* out_itv = out + NEDGE + 2 * KEDGE;
    float* out_iti = out + NEDGE + 2 * KEDGE + KITEM;

    k_proj<<<NE / 64, 128>>>(emb, WQ, noise);
    k_edge<<<EDGE_BLOCKS, 256>>>(head, tail, etype, rel);
    k_topk<<<NB_TOTAL, 256>>>(head, out, out_tkv, out_tki, out_itv, out_iti);
}